// round 17
// baseline (speedup 1.0000x reference)
#include <cuda_runtime.h>
#include <cuda_fp16.h>
#include <cstdint>
#include <math.h>

#define S_  2048
#define B_  4
#define D_  1024
#define H_  16
#define DH_ 64
#define F_  4096
#define M_  8192   // S_*B_
#define QKVS 3072  // fused qkv row stride

// ---------------- scratch (device globals; no allocation allowed) ------------
__device__ __half g_h   [M_ * D_];
__device__ __half g_qkv [(size_t)M_ * QKVS];
__device__ __half g_ctx [M_ * D_];
__device__ float  g_x1  [M_ * D_];
__device__ __half g_h2  [M_ * D_];
__device__ __half g_ff  [(size_t)M_ * F_];
// transposed (half) weights, [N, K] K-major
__device__ __half g_wqkvT[(size_t)QKVS * D_];  // rows: 0-1023 Wq*0.125, 1024-2047 Wk, 2048-3071 Wv
__device__ float  g_bqkv [QKVS];
__device__ __half g_woT[D_ * D_];
__device__ __half g_w1T[(size_t)F_ * D_];   // [4096,1024]
__device__ __half g_w2T[(size_t)D_ * F_];   // [1024,4096]

// ---------------- helpers -----------------------------------------------------
__device__ __forceinline__ uint32_t smem_u32(const void* p) {
    uint32_t a;
    asm("{ .reg .u64 t; cvta.to.shared.u64 t, %1; cvt.u32.u64 %0, t; }" : "=r"(a) : "l"(p));
    return a;
}
#define CP_ASYNC16(dst, src) \
    asm volatile("cp.async.cg.shared.global [%0], [%1], 16;" :: "r"(dst), "l"(src))
#define CP_COMMIT() asm volatile("cp.async.commit_group;" ::: "memory")

__device__ __forceinline__ void mma_f16(float* c, const uint32_t* a, const uint32_t* b) {
    asm volatile(
        "mma.sync.aligned.m16n8k16.row.col.f32.f16.f16.f32 "
        "{%0,%1,%2,%3}, {%4,%5,%6,%7}, {%8,%9}, {%0,%1,%2,%3};"
        : "+f"(c[0]), "+f"(c[1]), "+f"(c[2]), "+f"(c[3])
        : "r"(a[0]), "r"(a[1]), "r"(a[2]), "r"(a[3]), "r"(b[0]), "r"(b[1]));
}
__device__ __forceinline__ void ldmatrix_x4(uint32_t* r, uint32_t addr) {
    asm volatile("ldmatrix.sync.aligned.m8n8.x4.shared.b16 {%0,%1,%2,%3}, [%4];"
                 : "=r"(r[0]), "=r"(r[1]), "=r"(r[2]), "=r"(r[3]) : "r"(addr));
}
__device__ __forceinline__ void ldmatrix_x2_trans(uint32_t& r0, uint32_t& r1, uint32_t addr) {
    asm volatile("ldmatrix.sync.aligned.m8n8.x2.trans.shared.b16 {%0,%1}, [%2];"
                 : "=r"(r0), "=r"(r1) : "r"(addr));
}
__device__ __forceinline__ uint32_t h2_bits(__half2 h) {
    uint32_t u;
    *(__half2*)&u = h;
    return u;
}

// ---------------- fp16 mma.sync GEMM ------------------------------------------
// C[M,N] = A[M,K] @ Bt[N,K]^T (+epilogue). A,Bt half; accum fp32.
// 128x256 tile, 256 thr (8 warps 2x4, warp tile 64x64), K-chunk 64 halfs,
// 3-stage cp.async ring, ldmatrix fragments, 1 CTA/SM.
#define TM    128
#define TN    256
#define TK    64
#define NSTG  3
#define LDH   72                        // smem row stride in halfs (144B: conflict-free)
#define TILEA (128 * LDH)
#define TILEB (256 * LDH)
#define STGH  (TILEA + TILEB)
#define GEMM_SMEM (NSTG * STGH * 2)     // 165888 bytes

// EPI: 1 half(relu(+bias)) | 2 +bias+residual (float out) | 3 half(+bias)
template<int EPI, typename OutT>
__global__ void __launch_bounds__(256, 1)
gemm_mma(const __half* __restrict__ A, const __half* __restrict__ Bt,
         const float* __restrict__ bias, const float* __restrict__ res,
         OutT* __restrict__ C, int N, int K) {
    extern __shared__ __half smh[];

    const int tid  = threadIdx.x;
    const int lane = tid & 31, wid = tid >> 5;
    const int wm = wid & 1, wn = wid >> 1;         // 2(M) x 4(N); warp tile 64x64
    const int m0 = blockIdx.y * TM, n0 = blockIdx.x * TN;
    const int g = lane >> 2, t = lane & 3;
    const int CH = K / TK;

    float c[4][8][4];
    #pragma unroll
    for (int i = 0; i < 4; i++)
        #pragma unroll
        for (int j = 0; j < 8; j++)
            #pragma unroll
            for (int r = 0; r < 4; r++) c[i][j][r] = 0.f;

    // ldmatrix per-lane address components
    const int x4_row  = (lane & 15);            // row within 16-row group
    const int x4_koff = (lane >> 4) * 8;        // k-half select

    auto load_stage = [&](int cc, int s) {
        const __half* Ab = A  + (size_t)m0 * K + cc * TK;
        const __half* Bb = Bt + (size_t)n0 * K + cc * TK;
        __half* as = smh + s * STGH;
        __half* bs = as + TILEA;
        // A:128 rows + B:256 rows, 8 granules(16B) per row = 3072; 12/thread
        #pragma unroll
        for (int i = 0; i < 12; i++) {
            int gi = tid + 256 * i;             // 0..3071
            if (gi < 1024) {
                int r = gi >> 3, gc = gi & 7;
                CP_ASYNC16(smem_u32(as + r * LDH + gc * 8), Ab + (size_t)r * K + gc * 8);
            } else {
                int o = gi - 1024;
                int r = o >> 3, gc = o & 7;
                CP_ASYNC16(smem_u32(bs + r * LDH + gc * 8), Bb + (size_t)r * K + gc * 8);
            }
        }
        CP_COMMIT();
    };

    load_stage(0, 0);
    load_stage(1, 1);

    for (int cc = 0; cc < CH; cc++) {
        if (cc == CH - 1) asm volatile("cp.async.wait_group 0;" ::: "memory");
        else              asm volatile("cp.async.wait_group 1;" ::: "memory");
        __syncthreads();

        if (cc + 2 < CH) load_stage(cc + 2, (cc + 2) % NSTG);

        const __half* as = smh + (cc % NSTG) * STGH + (wm * 64) * LDH;
        const __half* bs = smh + (cc % NSTG) * STGH + TILEA + (wn * 64) * LDH;

        #pragma unroll
        for (int kc = 0; kc < 4; kc++) {           // 4 k-steps of 16 halfs
            uint32_t af[4][4], bq4[4][4];
            #pragma unroll
            for (int i = 0; i < 4; i++)
                ldmatrix_x4(af[i], smem_u32(as + (i * 16 + x4_row) * LDH + kc * 16 + x4_koff));
            #pragma unroll
            for (int j = 0; j < 4; j++)
                ldmatrix_x4(bq4[j], smem_u32(bs + (j * 16 + x4_row) * LDH + kc * 16 + x4_koff));
            #pragma unroll
            for (int i = 0; i < 4; i++)
                #pragma unroll
                for (int j = 0; j < 4; j++) {
                    uint32_t blo[2] = { bq4[j][0], bq4[j][2] };   // n-tile 2j
                    uint32_t bhi[2] = { bq4[j][1], bq4[j][3] };   // n-tile 2j+1
                    mma_f16(c[i][2 * j],     af[i], blo);
                    mma_f16(c[i][2 * j + 1], af[i], bhi);
                }
        }
    }

    #pragma unroll
    for (int i = 0; i < 4; i++) {
        const int r0 = m0 + wm * 64 + i * 16 + g;
        #pragma unroll
        for (int j = 0; j < 8; j++) {
            const int col = n0 + wn * 64 + j * 8 + 2 * t;
            float b0 = bias[col], b1 = bias[col + 1];
            float v0 = c[i][j][0] + b0, v1 = c[i][j][1] + b1;
            float v2 = c[i][j][2] + b0, v3 = c[i][j][3] + b1;
            if (EPI == 1) {
                v0 = fmaxf(v0, 0.f); v1 = fmaxf(v1, 0.f);
                v2 = fmaxf(v2, 0.f); v3 = fmaxf(v3, 0.f);
            }
            if (EPI == 2) {
                float2 ra = *(const float2*)(res + (size_t)r0 * N + col);
                float2 rb = *(const float2*)(res + (size_t)(r0 + 8) * N + col);
                v0 += ra.x; v1 += ra.y; v2 += rb.x; v3 += rb.y;
                *(float2*)((float*)C + (size_t)r0 * N + col)       = make_float2(v0, v1);
                *(float2*)((float*)C + (size_t)(r0 + 8) * N + col) = make_float2(v2, v3);
            } else {
                *(__half2*)((__half*)C + (size_t)r0 * N + col) =
                    __floats2half2_rn(v0, v1);
                *(__half2*)((__half*)C + (size_t)(r0 + 8) * N + col) =
                    __floats2half2_rn(v2, v3);
            }
        }
    }
}

// ---------------- weight transpose -> half (+scale fold) ----------------------
__global__ void transpose_half(const float* __restrict__ in, __half* __restrict__ out,
                               int K, int N, float scale) {
    __shared__ float t[32][33];
    int n0 = blockIdx.x * 32, k0 = blockIdx.y * 32;
    #pragma unroll
    for (int i = threadIdx.y; i < 32; i += 8)
        t[i][threadIdx.x] = in[(size_t)(k0 + i) * N + n0 + threadIdx.x];
    __syncthreads();
    #pragma unroll
    for (int i = threadIdx.y; i < 32; i += 8)
        out[(size_t)(n0 + i) * K + k0 + threadIdx.x] = __float2half_rn(t[threadIdx.x][i] * scale);
}

__global__ void concat_bias(const float* __restrict__ bq, const float* __restrict__ bk,
                            const float* __restrict__ bv, float* __restrict__ out) {
    int i = blockIdx.x * 256 + threadIdx.x;
    float v = (i < 1024) ? bq[i] * 0.125f : (i < 2048) ? bk[i - 1024] : bv[i - 2048];
    out[i] = v;
}

// ---------------- block reduction --------------------------------------------
__device__ __forceinline__ float blockReduceSum256(float val) {
    __shared__ float sh[8];
    #pragma unroll
    for (int o = 16; o; o >>= 1) val += __shfl_xor_sync(0xffffffffu, val, o);
    int w = threadIdx.x >> 5;
    if ((threadIdx.x & 31) == 0) sh[w] = val;
    __syncthreads();
    float tot = 0.f;
    #pragma unroll
    for (int i = 0; i < 8; i++) tot += sh[i];
    __syncthreads();
    return tot;
}

// ---------------- LayerNorm: f32 in -> half out -------------------------------
__global__ void ln_kernel(const float* __restrict__ x,
                          const float* __restrict__ g,
                          const float* __restrict__ b,
                          __half* __restrict__ out) {
    int row = blockIdx.x;
    const float4* xr = (const float4*)(x + (size_t)row * D_);
    float4 xv = xr[threadIdx.x];

    float s = xv.x + xv.y + xv.z + xv.w;
    float mean = blockReduceSum256(s) * (1.0f / D_);

    float dx0 = xv.x - mean, dx1 = xv.y - mean, dx2 = xv.z - mean, dx3 = xv.w - mean;
    float s2 = dx0*dx0 + dx1*dx1 + dx2*dx2 + dx3*dx3;
    float var = blockReduceSum256(s2) * (1.0f / D_);
    float inv = rsqrtf(var + 1e-5f);

    float4 gv = ((const float4*)g)[threadIdx.x];
    float4 bv = ((const float4*)b)[threadIdx.x];
    __half2 h0 = __floats2half2_rn(dx0 * inv * gv.x + bv.x, dx1 * inv * gv.y + bv.y);
    __half2 h1 = __floats2half2_rn(dx2 * inv * gv.z + bv.z, dx3 * inv * gv.w + bv.w);
    uint2 pk = make_uint2(h2_bits(h0), h2_bits(h1));
    *(uint2*)(out + (size_t)row * D_ + 4 * threadIdx.x) = pk;
}

// ---------------- Flash attention, fp16 mma.sync -------------------------------
// grid (S/128, B*H), 256 thr (8 warps x 16 Q rows). q/k/v half, fused buffer.
#define ASTH 72                         // smem row stride (halfs)
#define NKT (S_ / 64)
#define ATT_SMEM (5 * 128 * ASTH * 2)   // 92160 bytes

__global__ void __launch_bounds__(256, 1)
attn_mma(const __half* __restrict__ qkv, __half* __restrict__ ctx) {
    extern __shared__ __half smh[];
    __half* Qs = smh;                    // [128][ASTH]
    __half* Ps = smh + 128 * ASTH;       // [128][ASTH]
    __half* KV = smh + 256 * ASTH;       // 3 x [128][ASTH]: rows 0-63 K, 64-127 V

    const int tid = threadIdx.x;
    const int lane = tid & 31, wid = tid >> 5;
    const int g = lane >> 2, t = lane & 3;
    const int bh = blockIdx.y, b = bh >> 4, h = bh & 15;
    const int qt = blockIdx.x;
    const int colbase = h * 64;
    const __half* q = qkv;
    const __half* k = qkv + 1024;
    const __half* v = qkv + 2048;

    auto issue_kv = [&](int kt) {
        __half* st = KV + (kt % 3) * 128 * ASTH;
        #pragma unroll
        for (int j = 0; j < 4; j++) {
            int gi = tid + 256 * j;          // 0..1023
            int r = (gi & 511) >> 3, c8 = (gi & 7) << 3;
            const __half* src = (gi < 512)
                ? k + ((size_t)(kt * 64 + r) * B_ + b) * QKVS + colbase + c8
                : v + ((size_t)(kt * 64 + r) * B_ + b) * QKVS + colbase + c8;
            __half* dst = st + ((gi < 512) ? r : (64 + r)) * ASTH + c8;
            CP_ASYNC16(smem_u32(dst), src);
        }
        CP_COMMIT();
    };
    issue_kv(0);
    issue_kv(1);

    // load Q tile
    for (int i = tid; i < 128 * 8; i += 256) {
        int r = i >> 3, c8 = (i & 7) << 3;
        *(uint4*)(Qs + r * ASTH + c8) =
            *(const uint4*)(q + ((size_t)(qt * 128 + r) * B_ + b) * QKVS + colbase + c8);
    }
    __syncthreads();

    // Q fragments: 4 k-steps of 16 (DH=64)
    uint32_t qf[4][4];
    {
        const uint32_t* q0 = (const uint32_t*)(Qs + (wid * 16 + g) * ASTH);
        const uint32_t* q1 = (const uint32_t*)(Qs + (wid * 16 + g + 8) * ASTH);
        #pragma unroll
        for (int kc = 0; kc < 4; kc++) {
            qf[kc][0] = q0[kc * 8 + t];
            qf[kc][1] = q1[kc * 8 + t];
            qf[kc][2] = q0[kc * 8 + t + 4];
            qf[kc][3] = q1[kc * 8 + t + 4];
        }
    }

    float mr[2] = {-1e30f, -1e30f}, lr[2] = {0.f, 0.f};
    float O[8][4];
    #pragma unroll
    for (int nt = 0; nt < 8; nt++)
        #pragma unroll
        for (int r = 0; r < 4; r++) O[nt][r] = 0.f;

    __half* Pw0 = Ps + (wid * 16 + g) * ASTH;
    __half* Pw1 = Ps + (wid * 16 + g + 8) * ASTH;

    for (int kt = 0; kt < NKT; kt++) {
        if (kt == NKT - 1) asm volatile("cp.async.wait_group 0;" ::: "memory");
        else               asm volatile("cp.async.wait_group 1;" ::: "memory");
        __syncthreads();
        if (kt + 2 < NKT) issue_kv(kt + 2);

        const __half* Ks = KV + (kt % 3) * 128 * ASTH;
        const __half* Vs = Ks + 64 * ASTH;

        // S = Q @ K^T
        float s[8][4];
        #pragma unroll
        for (int nt = 0; nt < 8; nt++)
            #pragma unroll
            for (int r = 0; r < 4; r++) s[nt][r] = 0.f;

        #pragma unroll
        for (int kc = 0; kc < 4; kc++) {
            #pragma unroll
            for (int nt = 0; nt < 8; nt++) {
                const uint32_t* kp = (const uint32_t*)(Ks + (nt * 8 + g) * ASTH) + kc * 8 + t;
                uint32_t bf[2] = { kp[0], kp[4] };
                mma_f16(s[nt], qf[kc], bf);
            }
        }

        // online softmax (rows g and g+8)
        #pragma unroll
        for (int ro = 0; ro < 2; ro++) {
            float tmax = -1e30f;
            #pragma unroll
            for (int nt = 0; nt < 8; nt++)
                tmax = fmaxf(tmax, fmaxf(s[nt][2 * ro], s[nt][2 * ro + 1]));
            tmax = fmaxf(tmax, __shfl_xor_sync(0xffffffffu, tmax, 1));
            tmax = fmaxf(tmax, __shfl_xor_sync(0xffffffffu, tmax, 2));
            float newm = fmaxf(mr[ro], tmax);
            float corr = __expf(mr[ro] - newm);
            mr[ro] = newm;
            float sum = 0.f;
            __half* Pw = ro ? Pw1 : Pw0;
            #pragma unroll
            for (int nt = 0; nt < 8; nt++) {
                float p0 = __expf(s[nt][2 * ro]     - newm);
                float p1 = __expf(s[nt][2 * ro + 1] - newm);
                sum += p0 + p1;
                *(__half2*)(Pw + nt * 8 + 2 * t) = __floats2half2_rn(p0, p1);
                O[nt][2 * ro]     *= corr;
                O[nt][2 * ro + 1] *= corr;
            }
            sum += __shfl_xor_sync(0xffffffffu, sum, 1);
            sum += __shfl_xor_sync(0xffffffffu, sum, 2);
            lr[ro] = lr[ro] * corr + sum;
        }
        __syncwarp();

        // O += P @ V   (V fragments via ldmatrix.trans)
        #pragma unroll
        for (int kc = 0; kc < 4; kc++) {           // key k-steps of 16
            uint32_t pa[4];
            pa[0] = ((const uint32_t*)Pw0)[kc * 8 + t];
            pa[1] = ((const uint32_t*)Pw1)[kc * 8 + t];
            pa[2] = ((const uint32_t*)Pw0)[kc * 8 + t + 4];
            pa[3] = ((const uint32_t*)Pw1)[kc * 8 + t + 4];
            #pragma unroll
            for (int nt = 0; nt < 8; nt++) {
                int lrow = kc * 16 + (lane & 15);
                uint32_t addr = smem_u32(Vs + lrow * ASTH + nt * 8);
                uint32_t b0, b1;
                ldmatrix_x2_trans(b0, b1, addr);
                uint32_t vb[2] = { b0, b1 };
                mma_f16(O[nt], pa, vb);
            }
        }
        __syncwarp();
    }

    // normalize + store ctx (half)
    float inv0 = 1.f / lr[0], inv1 = 1.f / lr[1];
    const int r0 = qt * 128 + wid * 16 + g;
    #pragma unroll
    for (int nt = 0; nt < 8; nt++) {
        int col = colbase + nt * 8 + 2 * t;
        *(__half2*)(ctx + ((size_t)r0 * B_ + b) * D_ + col) =
            __floats2half2_rn(O[nt][0] * inv0, O[nt][1] * inv0);
        *(__half2*)(ctx + ((size_t)(r0 + 8) * B_ + b) * D_ + col) =
            __floats2half2_rn(O[nt][2] * inv1, O[nt][3] * inv1);
    }
}

// ---------------- launch ------------------------------------------------------
extern "C" void kernel_launch(void* const* d_in, const int* in_sizes, int n_in,
                              void* d_out, int out_size) {
    const float* x     = (const float*)d_in[0];
    const float* ln1_g = (const float*)d_in[1];
    const float* ln1_b = (const float*)d_in[2];
    const float* ln2_g = (const float*)d_in[3];
    const float* ln2_b = (const float*)d_in[4];
    const float* Wq    = (const float*)d_in[5];
    const float* bq    = (const float*)d_in[6];
    const float* Wk    = (const float*)d_in[7];
    const float* bk    = (const float*)d_in[8];
    const float* Wv    = (const float*)d_in[9];
    const float* bv    = (const float*)d_in[10];
    const float* Wo    = (const float*)d_in[11];
    const float* bo    = (const float*)d_in[12];
    const float* W1    = (const float*)d_in[13];
    const float* b1    = (const float*)d_in[14];
    const float* W2    = (const float*)d_in[15];
    const float* b2    = (const float*)d_in[16];
    float* out = (float*)d_out;

    __half *ph, *pqkv, *pctx, *ph2, *pff, *wqkvT, *woT, *w1T, *w2T;
    float *px1, *bqkv;
    cudaGetSymbolAddress((void**)&ph,   g_h);
    cudaGetSymbolAddress((void**)&pqkv, g_qkv);
    cudaGetSymbolAddress((void**)&pctx, g_ctx);
    cudaGetSymbolAddress((void**)&px1,  g_x1);
    cudaGetSymbolAddress((void**)&ph2,  g_h2);
    cudaGetSymbolAddress((void**)&pff,  g_ff);
    cudaGetSymbolAddress((void**)&wqkvT,g_wqkvT);
    cudaGetSymbolAddress((void**)&bqkv, g_bqkv);
    cudaGetSymbolAddress((void**)&woT,  g_woT);
    cudaGetSymbolAddress((void**)&w1T,  g_w1T);
    cudaGetSymbolAddress((void**)&w2T,  g_w2T);

    cudaFuncSetAttribute(attn_mma, cudaFuncAttributeMaxDynamicSharedMemorySize, ATT_SMEM);
    cudaFuncSetAttribute((gemm_mma<1, __half>), cudaFuncAttributeMaxDynamicSharedMemorySize, GEMM_SMEM);
    cudaFuncSetAttribute((gemm_mma<2, float>),  cudaFuncAttributeMaxDynamicSharedMemorySize, GEMM_SMEM);
    cudaFuncSetAttribute((gemm_mma<3, __half>), cudaFuncAttributeMaxDynamicSharedMemorySize, GEMM_SMEM);

    // 0. transpose weights -> half [N,K]; Wq scaled by 1/sqrt(DH) (exact pow2)
    dim3 tb(32, 8);
    transpose_half<<<dim3(D_/32, D_/32), tb>>>(Wq, wqkvT,            D_, D_, 0.125f);
    transpose_half<<<dim3(D_/32, D_/32), tb>>>(Wk, wqkvT + 1024*D_,  D_, D_, 1.0f);
    transpose_half<<<dim3(D_/32, D_/32), tb>>>(Wv, wqkvT + 2048*D_,  D_, D_, 1.0f);
    transpose_half<<<dim3(D_/32, D_/32), tb>>>(Wo, woT, D_, D_, 1.0f);
    transpose_half<<<dim3(F_/32, D_/32), tb>>>(W1, w1T, D_, F_, 1.0f);
    transpose_half<<<dim3(D_/32, F_/32), tb>>>(W2, w2T, F_, D_, 1.0f);
    concat_bias<<<QKVS/256, 256>>>(bq, bk, bv, bqkv);

    // 1. h = half(LN1(x))
    ln_kernel<<<M_, 256>>>(x, ln1_g, ln1_b, ph);

    // 2. fused qkv = half(h @ [Wq*s|Wk|Wv] + [bq*s|bk|bv])
    gemm_mma<3, __half><<<dim3(QKVS / TN, M_ / TM), 256, GEMM_SMEM>>>(ph, wqkvT, bqkv, nullptr, pqkv, QKVS, D_);

    // 3. flash attention (fp16 mma) -> ctx (half)
    attn_mma<<<dim3(S_ / 128, B_ * H_), 256, ATT_SMEM>>>(pqkv, pctx);

    // 4. x1 = x + ctx @ Wo + bo   (float out)
    dim3 gD(D_ / TN, M_ / TM);
    gemm_mma<2, float><<<gD, 256, GEMM_SMEM>>>(pctx, woT, bo, x, px1, D_, D_);

    // 5. h2 = half(LN2(x1))
    ln_kernel<<<M_, 256>>>(px1, ln2_g, ln2_b, ph2);

    // 6. ff = half(relu(h2 @ W1 + b1))
    gemm_mma<1, __half><<<dim3(F_ / TN, M_ / TM), 256, GEMM_SMEM>>>(ph2, w1T, b1, nullptr, pff, F_, D_);

    // 7. out = x1 + ff @ W2 + b2   (float out)
    gemm_mma<2, float><<<gD, 256, GEMM_SMEM>>>(pff, w2T, b2, px1, out, D_, F_);
}